// round 2
// baseline (speedup 1.0000x reference)
#include <cuda_runtime.h>

#define Nn   48
#define N2   2304
#define N3   110592
#define NVOL 128     // B*CIN = B*COUT
#define NIO  256     // CIN*COUT
#define MM   12

// ---- scratch (static device globals; no allocation anywhere) ----
__device__ float2 g_bufA[NVOL * N3];   // 113 MB complex ping
__device__ float2 g_bufB[NVOL * N3];   // 113 MB complex pong
__device__ float  g_X[NVOL * N3];      // DHT3(x)
__device__ float  g_Y[NIO * N3];       // DHT3(padded weights)
__device__ float  g_Z[NVOL * N3];      // mixed spectrum
// Y-stage complex temps alias the ping-pong buffers (Y stage runs first):
//   c1 (256*12*12*48 float2) lives in g_bufB, c2 (256*12*48*48 float2) in g_bufA.

__device__ __forceinline__ int wrap48(int j) { return (j >= 48) ? (j - 48) : j; }

// ---------------- Pass A: DFT along z (innermost), real -> complex ----------------
// in: [v][x][y][z] real. out: g_bufA [v][x][y][k3] complex. grid = NVOL*48 (v,x) slabs.
__global__ void __launch_bounds__(288) k_fft_z(const float* __restrict__ xin, int use_gz)
{
    __shared__ float  tile[48][48];   // [y][z]
    __shared__ float2 tw[48];         // (cos, sin)
    int slab = blockIdx.x;
    int v = slab / 48, xx = slab % 48;
    int tid = threadIdx.x;
    if (tid < 48) { float s, c; sincospif(tid * (2.0f / 48.0f), &s, &c); tw[tid] = make_float2(c, s); }
    const float* base = (use_gz ? (const float*)g_Z : xin) + (size_t)v * N3 + (size_t)xx * N2;
    for (int idx = tid; idx < N2; idx += 288) tile[idx / 48][idx % 48] = base[idx];
    __syncthreads();

    int k = tid % 48, yb = tid / 48;   // k fixed per thread (twiddle recurrence)
    float2* obase = g_bufA + (size_t)v * N3 + (size_t)xx * N2;
    #pragma unroll
    for (int it = 0; it < 8; ++it) {
        int y = yb * 8 + it;
        float ar = 0.f, ai = 0.f;
        int j = 0;
        #pragma unroll
        for (int z = 0; z < 48; ++z) {
            float vv = tile[y][z];
            float2 t = tw[j];
            ar = fmaf(t.x, vv, ar);        // Re(e^{-i th}) = cos
            ai = fmaf(-t.y, vv, ai);       // Im(e^{-i th}) = -sin
            j = wrap48(j + k);
        }
        obase[y * 48 + k] = make_float2(ar, ai);   // k innermost -> coalesced
    }
}

// ---------------- Pass B: DFT along y (middle), complex -> complex ----------------
// g_bufA [v][x][y][k3] -> g_bufB [v][x][k2][k3]. grid = NVOL*48 (v,x) slabs.
__global__ void __launch_bounds__(288) k_fft_y()
{
    __shared__ float2 tile[48][48];   // [y][k3]
    __shared__ float2 tw[48];
    int slab = blockIdx.x;
    int tid = threadIdx.x;
    if (tid < 48) { float s, c; sincospif(tid * (2.0f / 48.0f), &s, &c); tw[tid] = make_float2(c, s); }
    const float2* base = g_bufA + (size_t)slab * N2;
    for (int idx = tid; idx < N2; idx += 288) tile[idx / 48][idx % 48] = base[idx];
    __syncthreads();

    int z = tid % 48, kb = tid / 48;
    float2* obase = g_bufB + (size_t)slab * N2;
    #pragma unroll
    for (int it = 0; it < 8; ++it) {
        int k2 = kb * 8 + it;
        float ar = 0.f, ai = 0.f;
        int j = 0;
        #pragma unroll
        for (int y = 0; y < 48; ++y) {
            float2 vv = tile[y][z];
            float2 t = tw[j];
            ar = fmaf(t.x, vv.x, fmaf( t.y, vv.y, ar));   // c*vr + s*vi
            ai = fmaf(t.x, vv.y, fmaf(-t.y, vv.x, ai));   // c*vi - s*vr
            j = wrap48(j + k2);
        }
        obase[k2 * 48 + z] = make_float2(ar, ai);
    }
}

// ------- Pass C: DFT along x (outer) + Re-Im fold, complex -> real (DHT done) ------
// g_bufB [v][x][y][k3] -> out real [v][k1][y][k3]; out = (to_out? outp : g_X), scaled.
__global__ void __launch_bounds__(288) k_fft_x_fold(float* __restrict__ outp, int to_out, float scale)
{
    __shared__ float2 tile[48][48];   // [x][k3]
    __shared__ float2 tw[48];         // (cas+, cas-) = (c+s, c-s)
    int v = blockIdx.x / 48, y = blockIdx.x % 48;
    int tid = threadIdx.x;
    if (tid < 48) { float s, c; sincospif(tid * (2.0f / 48.0f), &s, &c); tw[tid] = make_float2(c + s, c - s); }
    const float2* base = g_bufB + (size_t)v * N3 + (size_t)y * 48;
    for (int idx = tid; idx < N2; idx += 288) {
        int xx = idx / 48, z = idx % 48;
        tile[xx][z] = base[(size_t)xx * N2 + z];
    }
    __syncthreads();

    float* ob = (to_out ? outp : (float*)g_X) + (size_t)v * N3 + (size_t)y * 48;
    int z = tid % 48, kb = tid / 48;
    #pragma unroll
    for (int it = 0; it < 8; ++it) {
        int k1 = kb * 8 + it;
        float a = 0.f;
        int j = 0;
        #pragma unroll
        for (int xx = 0; xx < 48; ++xx) {
            float2 vv = tile[xx][z];
            float2 t = tw[j];
            a = fmaf(t.x, vv.x, fmaf(-t.y, vv.y, a));   // cas(th)*re - cas(-th)*im
            j = wrap48(j + k1);
        }
        ob[(size_t)k1 * N2 + z] = a * scale;
    }
}

// ---------------- Y (kernel spectrum) stage: sparse 12^3 support ----------------
// c1[io][m1][m2][k3]  (in g_bufB), c2[io][m1][k2][k3] (in g_bufA), then g_Y real.
__global__ void __launch_bounds__(192) k_y1(const float* __restrict__ w)
{
    __shared__ float  wt[1728];
    __shared__ float2 tw[48];
    int io = blockIdx.x;
    int tid = threadIdx.x;
    if (tid < 48) { float s, c; sincospif(tid * (2.0f / 48.0f), &s, &c); tw[tid] = make_float2(c, s); }
    for (int idx = tid; idx < 1728; idx += 192) wt[idx] = w[(size_t)io * 1728 + idx];
    __syncthreads();

    float2* c1 = g_bufB;
    int k = tid % 48, mb = tid / 48;   // mb 0..3
    float2* ob = c1 + (size_t)io * (144 * 48);
    for (int it = 0; it < 36; ++it) {
        int mm = mb * 36 + it;         // m1*12+m2 in [0,144)
        float ar = 0.f, ai = 0.f;
        int j = 0;
        #pragma unroll
        for (int m3 = 0; m3 < 12; ++m3) {
            float vv = wt[mm * 12 + m3];
            float2 t = tw[j];
            ar = fmaf(t.x, vv, ar);
            ai = fmaf(-t.y, vv, ai);
            j = wrap48(j + k);
        }
        ob[mm * 48 + k] = make_float2(ar, ai);
    }
}

__global__ void __launch_bounds__(288) k_y2()
{
    __shared__ float2 tile[12][48];
    __shared__ float2 tw[48];
    int io = blockIdx.x / 12, m1 = blockIdx.x % 12;
    int tid = threadIdx.x;
    if (tid < 48) { float s, c; sincospif(tid * (2.0f / 48.0f), &s, &c); tw[tid] = make_float2(c, s); }
    const float2* c1 = g_bufB;
    const float2* base = c1 + (size_t)io * 6912 + (size_t)m1 * 576;
    for (int idx = tid; idx < 576; idx += 288) tile[idx / 48][idx % 48] = base[idx];
    __syncthreads();

    float2* c2 = g_bufA;
    int k3 = tid % 48, kb = tid / 48;
    float2* ob = c2 + (size_t)io * (12 * 2304) + (size_t)m1 * 2304;
    #pragma unroll
    for (int it = 0; it < 8; ++it) {
        int k2 = kb * 8 + it;
        float ar = 0.f, ai = 0.f;
        int j = 0;
        #pragma unroll
        for (int m2 = 0; m2 < 12; ++m2) {
            float2 vv = tile[m2][k3];
            float2 t = tw[j];
            ar = fmaf(t.x, vv.x, fmaf( t.y, vv.y, ar));
            ai = fmaf(t.x, vv.y, fmaf(-t.y, vv.x, ai));
            j = wrap48(j + k2);
        }
        ob[k2 * 48 + k3] = make_float2(ar, ai);
    }
}

__global__ void __launch_bounds__(288) k_y3()
{
    __shared__ float2 tile[12][48];
    __shared__ float2 tw[48];         // (cas+, cas-)
    int io = blockIdx.x / 48, k2 = blockIdx.x % 48;
    int tid = threadIdx.x;
    if (tid < 48) { float s, c; sincospif(tid * (2.0f / 48.0f), &s, &c); tw[tid] = make_float2(c + s, c - s); }
    const float2* c2 = g_bufA;
    const float2* base = c2 + (size_t)io * 27648 + (size_t)k2 * 48;
    for (int idx = tid; idx < 576; idx += 288) {
        int m1 = idx / 48, k3 = idx % 48;
        tile[m1][k3] = base[(size_t)m1 * 2304 + k3];
    }
    __syncthreads();

    int k3 = tid % 48, kb = tid / 48;
    float* ob = g_Y + (size_t)io * N3 + (size_t)k2 * 48;
    #pragma unroll
    for (int it = 0; it < 8; ++it) {
        int k1 = kb * 8 + it;
        float a = 0.f;
        int j = 0;
        #pragma unroll
        for (int m1 = 0; m1 < 12; ++m1) {
            float2 vv = tile[m1][k3];
            float2 t = tw[j];
            a = fmaf(t.x, vv.x, fmaf(-t.y, vv.y, a));
            j = wrap48(j + k1);
        }
        ob[(size_t)k1 * N2 + k3] = a;
    }
}

// ---------------- Mixing: Z[p] = 0.5*[(Xp+Xq)*Yp + (Xp-Xq)*Yq], q = (p? n-p : 0) ----------------
__global__ void __launch_bounds__(256) k_mix()
{
    __shared__ float Sx[16][132];   // [pp][i*8+b], row stride 132 (bank-safe, 16B aligned)
    __shared__ float Dx[16][132];
    int p0 = blockIdx.x * 16;
    int tid = threadIdx.x;

    for (int idx = tid; idx < 2048; idx += 256) {
        int bi = idx >> 4;          // b*16+i
        int pp = idx & 15;
        int p = p0 + pp;
        int q = (p == 0) ? 0 : (N3 - p);
        float xp = g_X[(size_t)bi * N3 + p];
        float xq = g_X[(size_t)bi * N3 + q];
        int b = bi >> 4, i = bi & 15;
        Sx[pp][i * 8 + b] = xp + xq;
        Dx[pp][i * 8 + b] = xp - xq;
    }
    __syncthreads();

    int o = tid >> 4, pp = tid & 15;
    int p = p0 + pp;
    int q = (p == 0) ? 0 : (N3 - p);
    float acc[8];
    #pragma unroll
    for (int b = 0; b < 8; ++b) acc[b] = 0.f;

    #pragma unroll
    for (int i = 0; i < 16; ++i) {
        float yp = g_Y[(size_t)(i * 16 + o) * N3 + p];
        float yq = g_Y[(size_t)(i * 16 + o) * N3 + q];
        const float4* sp = (const float4*)&Sx[pp][i * 8];
        const float4* dp = (const float4*)&Dx[pp][i * 8];
        float4 s0 = sp[0], s1 = sp[1];
        float4 d0 = dp[0], d1 = dp[1];
        acc[0] = fmaf(s0.x, yp, fmaf(d0.x, yq, acc[0]));
        acc[1] = fmaf(s0.y, yp, fmaf(d0.y, yq, acc[1]));
        acc[2] = fmaf(s0.z, yp, fmaf(d0.z, yq, acc[2]));
        acc[3] = fmaf(s0.w, yp, fmaf(d0.w, yq, acc[3]));
        acc[4] = fmaf(s1.x, yp, fmaf(d1.x, yq, acc[4]));
        acc[5] = fmaf(s1.y, yp, fmaf(d1.y, yq, acc[5]));
        acc[6] = fmaf(s1.z, yp, fmaf(d1.z, yq, acc[6]));
        acc[7] = fmaf(s1.w, yp, fmaf(d1.w, yq, acc[7]));
    }
    #pragma unroll
    for (int b = 0; b < 8; ++b)
        g_Z[(size_t)(b * 16 + o) * N3 + p] = 0.5f * acc[b];
}

extern "C" void kernel_launch(void* const* d_in, const int* in_sizes, int n_in,
                              void* d_out, int out_size)
{
    (void)in_sizes; (void)n_in; (void)out_size;
    const float* x = (const float*)d_in[0];
    // d_in[1] = error_signal (all zeros -> full modes; unused by reference math)
    const float* w = (const float*)d_in[2];
    float* outp = (float*)d_out;

    // Y = DHT3(zero-padded weights)   [uses g_bufB (c1) and g_bufA (c2) as temps]
    k_y1<<<NIO, 192>>>(w);
    k_y2<<<NIO * 12, 288>>>();
    k_y3<<<NIO * 48, 288>>>();

    // X = DHT3(x)
    k_fft_z<<<NVOL * 48, 288>>>(x, 0);
    k_fft_y<<<NVOL * 48, 288>>>();
    k_fft_x_fold<<<NVOL * 48, 288>>>(nullptr, 0, 1.0f);

    // Z = mix(X, Y)
    k_mix<<<N3 / 16, 256>>>();

    // out = DHT3(Z) / n
    k_fft_z<<<NVOL * 48, 288>>>(nullptr, 1);
    k_fft_y<<<NVOL * 48, 288>>>();
    k_fft_x_fold<<<NVOL * 48, 288>>>(outp, 1, 1.0f / (float)N3);
}

// round 4
// speedup vs baseline: 1.0005x; 1.0005x over previous
#include <cuda_runtime.h>

#define Nn   48
#define N2   2304
#define N3   110592
#define NVOL 128     // B*CIN = B*COUT
#define NIO  256     // CIN*COUT
#define MM   12

// ---- scratch (static device globals; no allocation anywhere) ----
__device__ float2 g_bufA[NVOL * N3];   // 113 MB complex ping
__device__ float2 g_bufB[NVOL * N3];   // 113 MB complex pong
__device__ float  g_X[NVOL * N3];      // DHT3(x)
__device__ float  g_Y[NIO * N3];       // DHT3(padded weights)
__device__ float  g_Z[NVOL * N3];      // mixed spectrum
// Y-stage complex temps alias the ping-pong buffers (Y stage runs first):
//   c1 (256*12*12*48 float2) lives in g_bufB, c2 (256*12*48*48 float2) in g_bufA.

__device__ __forceinline__ int wrap48(int j) { return (j >= 48) ? (j - 48) : j; }

// ---------------- Pass A: DFT along z (innermost), real -> complex ----------------
// in: [v][x][y][z] real. out: g_bufA [v][x][y][k3] complex. grid = NVOL*48 (v,x) slabs.
__global__ void __launch_bounds__(288) k_fft_z(const float* __restrict__ xin, int use_gz)
{
    __shared__ float  tile[48][48];   // [y][z]
    __shared__ float2 tw[48];         // (cos, sin)
    int slab = blockIdx.x;
    int v = slab / 48, xx = slab % 48;
    int tid = threadIdx.x;
    if (tid < 48) { float s, c; sincospif(tid * (2.0f / 48.0f), &s, &c); tw[tid] = make_float2(c, s); }
    const float* base = (use_gz ? (const float*)g_Z : xin) + (size_t)v * N3 + (size_t)xx * N2;
    for (int idx = tid; idx < N2; idx += 288) tile[idx / 48][idx % 48] = base[idx];
    __syncthreads();

    int k = tid % 48, yb = tid / 48;   // k fixed per thread (twiddle recurrence)
    float2* obase = g_bufA + (size_t)v * N3 + (size_t)xx * N2;
    #pragma unroll
    for (int it = 0; it < 8; ++it) {
        int y = yb * 8 + it;
        float ar = 0.f, ai = 0.f;
        int j = 0;
        #pragma unroll
        for (int z = 0; z < 48; ++z) {
            float vv = tile[y][z];
            float2 t = tw[j];
            ar = fmaf(t.x, vv, ar);        // Re(e^{-i th}) = cos
            ai = fmaf(-t.y, vv, ai);       // Im(e^{-i th}) = -sin
            j = wrap48(j + k);
        }
        obase[y * 48 + k] = make_float2(ar, ai);   // k innermost -> coalesced
    }
}

// ---------------- Pass B: DFT along y (middle), complex -> complex ----------------
// g_bufA [v][x][y][k3] -> g_bufB [v][x][k2][k3]. grid = NVOL*48 (v,x) slabs.
__global__ void __launch_bounds__(288) k_fft_y()
{
    __shared__ float2 tile[48][48];   // [y][k3]
    __shared__ float2 tw[48];
    int slab = blockIdx.x;
    int tid = threadIdx.x;
    if (tid < 48) { float s, c; sincospif(tid * (2.0f / 48.0f), &s, &c); tw[tid] = make_float2(c, s); }
    const float2* base = g_bufA + (size_t)slab * N2;
    for (int idx = tid; idx < N2; idx += 288) tile[idx / 48][idx % 48] = base[idx];
    __syncthreads();

    int z = tid % 48, kb = tid / 48;
    float2* obase = g_bufB + (size_t)slab * N2;
    #pragma unroll
    for (int it = 0; it < 8; ++it) {
        int k2 = kb * 8 + it;
        float ar = 0.f, ai = 0.f;
        int j = 0;
        #pragma unroll
        for (int y = 0; y < 48; ++y) {
            float2 vv = tile[y][z];
            float2 t = tw[j];
            ar = fmaf(t.x, vv.x, fmaf( t.y, vv.y, ar));   // c*vr + s*vi
            ai = fmaf(t.x, vv.y, fmaf(-t.y, vv.x, ai));   // c*vi - s*vr
            j = wrap48(j + k2);
        }
        obase[k2 * 48 + z] = make_float2(ar, ai);
    }
}

// ------- Pass C: DFT along x (outer) + Re-Im fold, complex -> real (DHT done) ------
// g_bufB [v][x][y][k3] -> out real [v][k1][y][k3]; out = (to_out? outp : g_X), scaled.
__global__ void __launch_bounds__(288) k_fft_x_fold(float* __restrict__ outp, int to_out, float scale)
{
    __shared__ float2 tile[48][48];   // [x][k3]
    __shared__ float2 tw[48];         // (cas+, cas-) = (c+s, c-s)
    int v = blockIdx.x / 48, y = blockIdx.x % 48;
    int tid = threadIdx.x;
    if (tid < 48) { float s, c; sincospif(tid * (2.0f / 48.0f), &s, &c); tw[tid] = make_float2(c + s, c - s); }
    const float2* base = g_bufB + (size_t)v * N3 + (size_t)y * 48;
    for (int idx = tid; idx < N2; idx += 288) {
        int xx = idx / 48, z = idx % 48;
        tile[xx][z] = base[(size_t)xx * N2 + z];
    }
    __syncthreads();

    float* ob = (to_out ? outp : (float*)g_X) + (size_t)v * N3 + (size_t)y * 48;
    int z = tid % 48, kb = tid / 48;
    #pragma unroll
    for (int it = 0; it < 8; ++it) {
        int k1 = kb * 8 + it;
        float a = 0.f;
        int j = 0;
        #pragma unroll
        for (int xx = 0; xx < 48; ++xx) {
            float2 vv = tile[xx][z];
            float2 t = tw[j];
            a = fmaf(t.x, vv.x, fmaf(-t.y, vv.y, a));   // cas(th)*re - cas(-th)*im
            j = wrap48(j + k1);
        }
        ob[(size_t)k1 * N2 + z] = a * scale;
    }
}

// ---------------- Y (kernel spectrum) stage: sparse 12^3 support ----------------
// c1[io][m1][m2][k3]  (in g_bufB), c2[io][m1][k2][k3] (in g_bufA), then g_Y real.
__global__ void __launch_bounds__(192) k_y1(const float* __restrict__ w)
{
    __shared__ float  wt[1728];
    __shared__ float2 tw[48];
    int io = blockIdx.x;
    int tid = threadIdx.x;
    if (tid < 48) { float s, c; sincospif(tid * (2.0f / 48.0f), &s, &c); tw[tid] = make_float2(c, s); }
    for (int idx = tid; idx < 1728; idx += 192) wt[idx] = w[(size_t)io * 1728 + idx];
    __syncthreads();

    float2* c1 = g_bufB;
    int k = tid % 48, mb = tid / 48;   // mb 0..3
    float2* ob = c1 + (size_t)io * (144 * 48);
    for (int it = 0; it < 36; ++it) {
        int mm = mb * 36 + it;         // m1*12+m2 in [0,144)
        float ar = 0.f, ai = 0.f;
        int j = 0;
        #pragma unroll
        for (int m3 = 0; m3 < 12; ++m3) {
            float vv = wt[mm * 12 + m3];
            float2 t = tw[j];
            ar = fmaf(t.x, vv, ar);
            ai = fmaf(-t.y, vv, ai);
            j = wrap48(j + k);
        }
        ob[mm * 48 + k] = make_float2(ar, ai);
    }
}

__global__ void __launch_bounds__(288) k_y2()
{
    __shared__ float2 tile[12][48];
    __shared__ float2 tw[48];
    int io = blockIdx.x / 12, m1 = blockIdx.x % 12;
    int tid = threadIdx.x;
    if (tid < 48) { float s, c; sincospif(tid * (2.0f / 48.0f), &s, &c); tw[tid] = make_float2(c, s); }
    const float2* c1 = g_bufB;
    const float2* base = c1 + (size_t)io * 6912 + (size_t)m1 * 576;
    for (int idx = tid; idx < 576; idx += 288) tile[idx / 48][idx % 48] = base[idx];
    __syncthreads();

    float2* c2 = g_bufA;
    int k3 = tid % 48, kb = tid / 48;
    float2* ob = c2 + (size_t)io * (12 * 2304) + (size_t)m1 * 2304;
    #pragma unroll
    for (int it = 0; it < 8; ++it) {
        int k2 = kb * 8 + it;
        float ar = 0.f, ai = 0.f;
        int j = 0;
        #pragma unroll
        for (int m2 = 0; m2 < 12; ++m2) {
            float2 vv = tile[m2][k3];
            float2 t = tw[j];
            ar = fmaf(t.x, vv.x, fmaf( t.y, vv.y, ar));
            ai = fmaf(t.x, vv.y, fmaf(-t.y, vv.x, ai));
            j = wrap48(j + k2);
        }
        ob[k2 * 48 + k3] = make_float2(ar, ai);
    }
}

__global__ void __launch_bounds__(288) k_y3()
{
    __shared__ float2 tile[12][48];
    __shared__ float2 tw[48];         // (cas+, cas-)
    int io = blockIdx.x / 48, k2 = blockIdx.x % 48;
    int tid = threadIdx.x;
    if (tid < 48) { float s, c; sincospif(tid * (2.0f / 48.0f), &s, &c); tw[tid] = make_float2(c + s, c - s); }
    const float2* c2 = g_bufA;
    const float2* base = c2 + (size_t)io * 27648 + (size_t)k2 * 48;
    for (int idx = tid; idx < 576; idx += 288) {
        int m1 = idx / 48, k3 = idx % 48;
        tile[m1][k3] = base[(size_t)m1 * 2304 + k3];
    }
    __syncthreads();

    int k3 = tid % 48, kb = tid / 48;
    float* ob = g_Y + (size_t)io * N3 + (size_t)k2 * 48;
    #pragma unroll
    for (int it = 0; it < 8; ++it) {
        int k1 = kb * 8 + it;
        float a = 0.f;
        int j = 0;
        #pragma unroll
        for (int m1 = 0; m1 < 12; ++m1) {
            float2 vv = tile[m1][k3];
            float2 t = tw[j];
            a = fmaf(t.x, vv.x, fmaf(-t.y, vv.y, a));
            j = wrap48(j + k1);
        }
        ob[(size_t)k1 * N2 + k3] = a;
    }
}

// ---------------- Mixing: Z[p] = 0.5*[(Xp+Xq)*Yp + (Xp-Xq)*Yq], q = (p? n-p : 0) ----------------
__global__ void __launch_bounds__(256) k_mix()
{
    __shared__ float Sx[16][132];   // [pp][i*8+b], row stride 132 (bank-safe, 16B aligned)
    __shared__ float Dx[16][132];
    int p0 = blockIdx.x * 16;
    int tid = threadIdx.x;

    for (int idx = tid; idx < 2048; idx += 256) {
        int bi = idx >> 4;          // b*16+i
        int pp = idx & 15;
        int p = p0 + pp;
        int q = (p == 0) ? 0 : (N3 - p);
        float xp = g_X[(size_t)bi * N3 + p];
        float xq = g_X[(size_t)bi * N3 + q];
        int b = bi >> 4, i = bi & 15;
        Sx[pp][i * 8 + b] = xp + xq;
        Dx[pp][i * 8 + b] = xp - xq;
    }
    __syncthreads();

    int o = tid >> 4, pp = tid & 15;
    int p = p0 + pp;
    int q = (p == 0) ? 0 : (N3 - p);
    float acc[8];
    #pragma unroll
    for (int b = 0; b < 8; ++b) acc[b] = 0.f;

    #pragma unroll
    for (int i = 0; i < 16; ++i) {
        float yp = g_Y[(size_t)(i * 16 + o) * N3 + p];
        float yq = g_Y[(size_t)(i * 16 + o) * N3 + q];
        const float4* sp = (const float4*)&Sx[pp][i * 8];
        const float4* dp = (const float4*)&Dx[pp][i * 8];
        float4 s0 = sp[0], s1 = sp[1];
        float4 d0 = dp[0], d1 = dp[1];
        acc[0] = fmaf(s0.x, yp, fmaf(d0.x, yq, acc[0]));
        acc[1] = fmaf(s0.y, yp, fmaf(d0.y, yq, acc[1]));
        acc[2] = fmaf(s0.z, yp, fmaf(d0.z, yq, acc[2]));
        acc[3] = fmaf(s0.w, yp, fmaf(d0.w, yq, acc[3]));
        acc[4] = fmaf(s1.x, yp, fmaf(d1.x, yq, acc[4]));
        acc[5] = fmaf(s1.y, yp, fmaf(d1.y, yq, acc[5]));
        acc[6] = fmaf(s1.z, yp, fmaf(d1.z, yq, acc[6]));
        acc[7] = fmaf(s1.w, yp, fmaf(d1.w, yq, acc[7]));
    }
    #pragma unroll
    for (int b = 0; b < 8; ++b)
        g_Z[(size_t)(b * 16 + o) * N3 + p] = 0.5f * acc[b];
}

extern "C" void kernel_launch(void* const* d_in, const int* in_sizes, int n_in,
                              void* d_out, int out_size)
{
    (void)in_sizes; (void)n_in; (void)out_size;
    const float* x = (const float*)d_in[0];
    // d_in[1] = error_signal (all zeros -> full modes; unused by reference math)
    const float* w = (const float*)d_in[2];
    float* outp = (float*)d_out;

    // Y = DHT3(zero-padded weights)   [uses g_bufB (c1) and g_bufA (c2) as temps]
    k_y1<<<NIO, 192>>>(w);
    k_y2<<<NIO * 12, 288>>>();
    k_y3<<<NIO * 48, 288>>>();

    // X = DHT3(x)
    k_fft_z<<<NVOL * 48, 288>>>(x, 0);
    k_fft_y<<<NVOL * 48, 288>>>();
    k_fft_x_fold<<<NVOL * 48, 288>>>(nullptr, 0, 1.0f);

    // Z = mix(X, Y)
    k_mix<<<N3 / 16, 256>>>();

    // out = DHT3(Z) / n
    k_fft_z<<<NVOL * 48, 288>>>(nullptr, 1);
    k_fft_y<<<NVOL * 48, 288>>>();
    k_fft_x_fold<<<NVOL * 48, 288>>>(outp, 1, 1.0f / (float)N3);
}

// round 5
// speedup vs baseline: 1.0022x; 1.0017x over previous
#include <cuda_runtime.h>

#define Nn   48
#define N2   2304
#define N3   110592
#define NVOL 128     // B*CIN = B*COUT
#define NIO  256     // CIN*COUT
#define MM   12

// ---- scratch (static device globals; no allocation anywhere) ----
__device__ float2 g_bufA[NVOL * N3];   // 113 MB complex ping
__device__ float2 g_bufB[NVOL * N3];   // 113 MB complex pong
__device__ float  g_X[NVOL * N3];      // DHT3(x)
__device__ float  g_Y[NIO * N3];       // DHT3(padded weights)
__device__ float  g_Z[NVOL * N3];      // mixed spectrum
// Y-stage complex temps alias the ping-pong buffers (Y stage runs first):
//   c1 (256*12*12*48 float2) lives in g_bufB, c2 (256*12*48*48 float2) in g_bufA.

__device__ __forceinline__ int wrap48(int j) { return (j >= 48) ? (j - 48) : j; }

// ---------------- Pass A: DFT along z (innermost), real -> complex ----------------
// in: [v][x][y][z] real. out: g_bufA [v][x][y][k3] complex. grid = NVOL*48 (v,x) slabs.
__global__ void __launch_bounds__(288) k_fft_z(const float* __restrict__ xin, int use_gz)
{
    __shared__ float  tile[48][48];   // [y][z]
    __shared__ float2 tw[48];         // (cos, sin)
    int slab = blockIdx.x;
    int v = slab / 48, xx = slab % 48;
    int tid = threadIdx.x;
    if (tid < 48) { float s, c; sincospif(tid * (2.0f / 48.0f), &s, &c); tw[tid] = make_float2(c, s); }
    const float* base = (use_gz ? (const float*)g_Z : xin) + (size_t)v * N3 + (size_t)xx * N2;
    for (int idx = tid; idx < N2; idx += 288) tile[idx / 48][idx % 48] = base[idx];
    __syncthreads();

    int k = tid % 48, yb = tid / 48;   // k fixed per thread (twiddle recurrence)
    float2* obase = g_bufA + (size_t)v * N3 + (size_t)xx * N2;
    #pragma unroll
    for (int it = 0; it < 8; ++it) {
        int y = yb * 8 + it;
        float ar = 0.f, ai = 0.f;
        int j = 0;
        #pragma unroll
        for (int z = 0; z < 48; ++z) {
            float vv = tile[y][z];
            float2 t = tw[j];
            ar = fmaf(t.x, vv, ar);        // Re(e^{-i th}) = cos
            ai = fmaf(-t.y, vv, ai);       // Im(e^{-i th}) = -sin
            j = wrap48(j + k);
        }
        obase[y * 48 + k] = make_float2(ar, ai);   // k innermost -> coalesced
    }
}

// ---------------- Pass B: DFT along y (middle), complex -> complex ----------------
// g_bufA [v][x][y][k3] -> g_bufB [v][x][k2][k3]. grid = NVOL*48 (v,x) slabs.
__global__ void __launch_bounds__(288) k_fft_y()
{
    __shared__ float2 tile[48][48];   // [y][k3]
    __shared__ float2 tw[48];
    int slab = blockIdx.x;
    int tid = threadIdx.x;
    if (tid < 48) { float s, c; sincospif(tid * (2.0f / 48.0f), &s, &c); tw[tid] = make_float2(c, s); }
    const float2* base = g_bufA + (size_t)slab * N2;
    for (int idx = tid; idx < N2; idx += 288) tile[idx / 48][idx % 48] = base[idx];
    __syncthreads();

    int z = tid % 48, kb = tid / 48;
    float2* obase = g_bufB + (size_t)slab * N2;
    #pragma unroll
    for (int it = 0; it < 8; ++it) {
        int k2 = kb * 8 + it;
        float ar = 0.f, ai = 0.f;
        int j = 0;
        #pragma unroll
        for (int y = 0; y < 48; ++y) {
            float2 vv = tile[y][z];
            float2 t = tw[j];
            ar = fmaf(t.x, vv.x, fmaf( t.y, vv.y, ar));   // c*vr + s*vi
            ai = fmaf(t.x, vv.y, fmaf(-t.y, vv.x, ai));   // c*vi - s*vr
            j = wrap48(j + k2);
        }
        obase[k2 * 48 + z] = make_float2(ar, ai);
    }
}

// ------- Pass C: DFT along x (outer) + Re-Im fold, complex -> real (DHT done) ------
// g_bufB [v][x][y][k3] -> out real [v][k1][y][k3]; out = (to_out? outp : g_X), scaled.
__global__ void __launch_bounds__(288) k_fft_x_fold(float* __restrict__ outp, int to_out, float scale)
{
    __shared__ float2 tile[48][48];   // [x][k3]
    __shared__ float2 tw[48];         // (cas+, cas-) = (c+s, c-s)
    int v = blockIdx.x / 48, y = blockIdx.x % 48;
    int tid = threadIdx.x;
    if (tid < 48) { float s, c; sincospif(tid * (2.0f / 48.0f), &s, &c); tw[tid] = make_float2(c + s, c - s); }
    const float2* base = g_bufB + (size_t)v * N3 + (size_t)y * 48;
    for (int idx = tid; idx < N2; idx += 288) {
        int xx = idx / 48, z = idx % 48;
        tile[xx][z] = base[(size_t)xx * N2 + z];
    }
    __syncthreads();

    float* ob = (to_out ? outp : (float*)g_X) + (size_t)v * N3 + (size_t)y * 48;
    int z = tid % 48, kb = tid / 48;
    #pragma unroll
    for (int it = 0; it < 8; ++it) {
        int k1 = kb * 8 + it;
        float a = 0.f;
        int j = 0;
        #pragma unroll
        for (int xx = 0; xx < 48; ++xx) {
            float2 vv = tile[xx][z];
            float2 t = tw[j];
            a = fmaf(t.x, vv.x, fmaf(-t.y, vv.y, a));   // cas(th)*re - cas(-th)*im
            j = wrap48(j + k1);
        }
        ob[(size_t)k1 * N2 + z] = a * scale;
    }
}

// ---------------- Y (kernel spectrum) stage: sparse 12^3 support ----------------
// c1[io][m1][m2][k3]  (in g_bufB), c2[io][m1][k2][k3] (in g_bufA), then g_Y real.
__global__ void __launch_bounds__(192) k_y1(const float* __restrict__ w)
{
    __shared__ float  wt[1728];
    __shared__ float2 tw[48];
    int io = blockIdx.x;
    int tid = threadIdx.x;
    if (tid < 48) { float s, c; sincospif(tid * (2.0f / 48.0f), &s, &c); tw[tid] = make_float2(c, s); }
    for (int idx = tid; idx < 1728; idx += 192) wt[idx] = w[(size_t)io * 1728 + idx];
    __syncthreads();

    float2* c1 = g_bufB;
    int k = tid % 48, mb = tid / 48;   // mb 0..3
    float2* ob = c1 + (size_t)io * (144 * 48);
    for (int it = 0; it < 36; ++it) {
        int mm = mb * 36 + it;         // m1*12+m2 in [0,144)
        float ar = 0.f, ai = 0.f;
        int j = 0;
        #pragma unroll
        for (int m3 = 0; m3 < 12; ++m3) {
            float vv = wt[mm * 12 + m3];
            float2 t = tw[j];
            ar = fmaf(t.x, vv, ar);
            ai = fmaf(-t.y, vv, ai);
            j = wrap48(j + k);
        }
        ob[mm * 48 + k] = make_float2(ar, ai);
    }
}

__global__ void __launch_bounds__(288) k_y2()
{
    __shared__ float2 tile[12][48];
    __shared__ float2 tw[48];
    int io = blockIdx.x / 12, m1 = blockIdx.x % 12;
    int tid = threadIdx.x;
    if (tid < 48) { float s, c; sincospif(tid * (2.0f / 48.0f), &s, &c); tw[tid] = make_float2(c, s); }
    const float2* c1 = g_bufB;
    const float2* base = c1 + (size_t)io * 6912 + (size_t)m1 * 576;
    for (int idx = tid; idx < 576; idx += 288) tile[idx / 48][idx % 48] = base[idx];
    __syncthreads();

    float2* c2 = g_bufA;
    int k3 = tid % 48, kb = tid / 48;
    float2* ob = c2 + (size_t)io * (12 * 2304) + (size_t)m1 * 2304;
    #pragma unroll
    for (int it = 0; it < 8; ++it) {
        int k2 = kb * 8 + it;
        float ar = 0.f, ai = 0.f;
        int j = 0;
        #pragma unroll
        for (int m2 = 0; m2 < 12; ++m2) {
            float2 vv = tile[m2][k3];
            float2 t = tw[j];
            ar = fmaf(t.x, vv.x, fmaf( t.y, vv.y, ar));
            ai = fmaf(t.x, vv.y, fmaf(-t.y, vv.x, ai));
            j = wrap48(j + k2);
        }
        ob[k2 * 48 + k3] = make_float2(ar, ai);
    }
}

__global__ void __launch_bounds__(288) k_y3()
{
    __shared__ float2 tile[12][48];
    __shared__ float2 tw[48];         // (cas+, cas-)
    int io = blockIdx.x / 48, k2 = blockIdx.x % 48;
    int tid = threadIdx.x;
    if (tid < 48) { float s, c; sincospif(tid * (2.0f / 48.0f), &s, &c); tw[tid] = make_float2(c + s, c - s); }
    const float2* c2 = g_bufA;
    const float2* base = c2 + (size_t)io * 27648 + (size_t)k2 * 48;
    for (int idx = tid; idx < 576; idx += 288) {
        int m1 = idx / 48, k3 = idx % 48;
        tile[m1][k3] = base[(size_t)m1 * 2304 + k3];
    }
    __syncthreads();

    int k3 = tid % 48, kb = tid / 48;
    float* ob = g_Y + (size_t)io * N3 + (size_t)k2 * 48;
    #pragma unroll
    for (int it = 0; it < 8; ++it) {
        int k1 = kb * 8 + it;
        float a = 0.f;
        int j = 0;
        #pragma unroll
        for (int m1 = 0; m1 < 12; ++m1) {
            float2 vv = tile[m1][k3];
            float2 t = tw[j];
            a = fmaf(t.x, vv.x, fmaf(-t.y, vv.y, a));
            j = wrap48(j + k1);
        }
        ob[(size_t)k1 * N2 + k3] = a;
    }
}

// ---------------- Mixing: Z[p] = 0.5*[(Xp+Xq)*Yp + (Xp-Xq)*Yq], q = (p? n-p : 0) ----------------
__global__ void __launch_bounds__(256) k_mix()
{
    __shared__ float Sx[16][132];   // [pp][i*8+b], row stride 132 (bank-safe, 16B aligned)
    __shared__ float Dx[16][132];
    int p0 = blockIdx.x * 16;
    int tid = threadIdx.x;

    for (int idx = tid; idx < 2048; idx += 256) {
        int bi = idx >> 4;          // b*16+i
        int pp = idx & 15;
        int p = p0 + pp;
        int q = (p == 0) ? 0 : (N3 - p);
        float xp = g_X[(size_t)bi * N3 + p];
        float xq = g_X[(size_t)bi * N3 + q];
        int b = bi >> 4, i = bi & 15;
        Sx[pp][i * 8 + b] = xp + xq;
        Dx[pp][i * 8 + b] = xp - xq;
    }
    __syncthreads();

    int o = tid >> 4, pp = tid & 15;
    int p = p0 + pp;
    int q = (p == 0) ? 0 : (N3 - p);
    float acc[8];
    #pragma unroll
    for (int b = 0; b < 8; ++b) acc[b] = 0.f;

    #pragma unroll
    for (int i = 0; i < 16; ++i) {
        float yp = g_Y[(size_t)(i * 16 + o) * N3 + p];
        float yq = g_Y[(size_t)(i * 16 + o) * N3 + q];
        const float4* sp = (const float4*)&Sx[pp][i * 8];
        const float4* dp = (const float4*)&Dx[pp][i * 8];
        float4 s0 = sp[0], s1 = sp[1];
        float4 d0 = dp[0], d1 = dp[1];
        acc[0] = fmaf(s0.x, yp, fmaf(d0.x, yq, acc[0]));
        acc[1] = fmaf(s0.y, yp, fmaf(d0.y, yq, acc[1]));
        acc[2] = fmaf(s0.z, yp, fmaf(d0.z, yq, acc[2]));
        acc[3] = fmaf(s0.w, yp, fmaf(d0.w, yq, acc[3]));
        acc[4] = fmaf(s1.x, yp, fmaf(d1.x, yq, acc[4]));
        acc[5] = fmaf(s1.y, yp, fmaf(d1.y, yq, acc[5]));
        acc[6] = fmaf(s1.z, yp, fmaf(d1.z, yq, acc[6]));
        acc[7] = fmaf(s1.w, yp, fmaf(d1.w, yq, acc[7]));
    }
    #pragma unroll
    for (int b = 0; b < 8; ++b)
        g_Z[(size_t)(b * 16 + o) * N3 + p] = 0.5f * acc[b];
}

extern "C" void kernel_launch(void* const* d_in, const int* in_sizes, int n_in,
                              void* d_out, int out_size)
{
    (void)in_sizes; (void)n_in; (void)out_size;
    const float* x = (const float*)d_in[0];
    // d_in[1] = error_signal (all zeros -> full modes; unused by reference math)
    const float* w = (const float*)d_in[2];
    float* outp = (float*)d_out;

    // Y = DHT3(zero-padded weights)   [uses g_bufB (c1) and g_bufA (c2) as temps]
    k_y1<<<NIO, 192>>>(w);
    k_y2<<<NIO * 12, 288>>>();
    k_y3<<<NIO * 48, 288>>>();

    // X = DHT3(x)
    k_fft_z<<<NVOL * 48, 288>>>(x, 0);
    k_fft_y<<<NVOL * 48, 288>>>();
    k_fft_x_fold<<<NVOL * 48, 288>>>(nullptr, 0, 1.0f);

    // Z = mix(X, Y)
    k_mix<<<N3 / 16, 256>>>();

    // out = DHT3(Z) / n
    k_fft_z<<<NVOL * 48, 288>>>(nullptr, 1);
    k_fft_y<<<NVOL * 48, 288>>>();
    k_fft_x_fold<<<NVOL * 48, 288>>>(outp, 1, 1.0f / (float)N3);
}

// round 8
// speedup vs baseline: 1.0024x; 1.0002x over previous
#include <cuda_runtime.h>

#define Nn   48
#define N2   2304
#define N3   110592
#define NVOL 128     // B*CIN = B*COUT
#define NIO  256     // CIN*COUT
#define MM   12

// ---- scratch (static device globals; no allocation anywhere) ----
__device__ float2 g_bufA[NVOL * N3];   // 113 MB complex ping
__device__ float2 g_bufB[NVOL * N3];   // 113 MB complex pong
__device__ float  g_X[NVOL * N3];      // DHT3(x)
__device__ float  g_Y[NIO * N3];       // DHT3(padded weights)
__device__ float  g_Z[NVOL * N3];      // mixed spectrum
// Y-stage complex temps alias the ping-pong buffers (Y stage runs first):
//   c1 (256*12*12*48 float2) lives in g_bufB, c2 (256*12*48*48 float2) in g_bufA.

__device__ __forceinline__ int wrap48(int j) { return (j >= 48) ? (j - 48) : j; }

// ---------------- Pass A: DFT along z (innermost), real -> complex ----------------
// in: [v][x][y][z] real. out: g_bufA [v][x][y][k3] complex. grid = NVOL*48 (v,x) slabs.
__global__ void __launch_bounds__(288) k_fft_z(const float* __restrict__ xin, int use_gz)
{
    __shared__ float  tile[48][48];   // [y][z]
    __shared__ float2 tw[48];         // (cos, sin)
    int slab = blockIdx.x;
    int v = slab / 48, xx = slab % 48;
    int tid = threadIdx.x;
    if (tid < 48) { float s, c; sincospif(tid * (2.0f / 48.0f), &s, &c); tw[tid] = make_float2(c, s); }
    const float* base = (use_gz ? (const float*)g_Z : xin) + (size_t)v * N3 + (size_t)xx * N2;
    for (int idx = tid; idx < N2; idx += 288) tile[idx / 48][idx % 48] = base[idx];
    __syncthreads();

    int k = tid % 48, yb = tid / 48;   // k fixed per thread (twiddle recurrence)
    float2* obase = g_bufA + (size_t)v * N3 + (size_t)xx * N2;
    #pragma unroll
    for (int it = 0; it < 8; ++it) {
        int y = yb * 8 + it;
        float ar = 0.f, ai = 0.f;
        int j = 0;
        #pragma unroll
        for (int z = 0; z < 48; ++z) {
            float vv = tile[y][z];
            float2 t = tw[j];
            ar = fmaf(t.x, vv, ar);        // Re(e^{-i th}) = cos
            ai = fmaf(-t.y, vv, ai);       // Im(e^{-i th}) = -sin
            j = wrap48(j + k);
        }
        obase[y * 48 + k] = make_float2(ar, ai);   // k innermost -> coalesced
    }
}

// ---------------- Pass B: DFT along y (middle), complex -> complex ----------------
// g_bufA [v][x][y][k3] -> g_bufB [v][x][k2][k3]. grid = NVOL*48 (v,x) slabs.
__global__ void __launch_bounds__(288) k_fft_y()
{
    __shared__ float2 tile[48][48];   // [y][k3]
    __shared__ float2 tw[48];
    int slab = blockIdx.x;
    int tid = threadIdx.x;
    if (tid < 48) { float s, c; sincospif(tid * (2.0f / 48.0f), &s, &c); tw[tid] = make_float2(c, s); }
    const float2* base = g_bufA + (size_t)slab * N2;
    for (int idx = tid; idx < N2; idx += 288) tile[idx / 48][idx % 48] = base[idx];
    __syncthreads();

    int z = tid % 48, kb = tid / 48;
    float2* obase = g_bufB + (size_t)slab * N2;
    #pragma unroll
    for (int it = 0; it < 8; ++it) {
        int k2 = kb * 8 + it;
        float ar = 0.f, ai = 0.f;
        int j = 0;
        #pragma unroll
        for (int y = 0; y < 48; ++y) {
            float2 vv = tile[y][z];
            float2 t = tw[j];
            ar = fmaf(t.x, vv.x, fmaf( t.y, vv.y, ar));   // c*vr + s*vi
            ai = fmaf(t.x, vv.y, fmaf(-t.y, vv.x, ai));   // c*vi - s*vr
            j = wrap48(j + k2);
        }
        obase[k2 * 48 + z] = make_float2(ar, ai);
    }
}

// ------- Pass C: DFT along x (outer) + Re-Im fold, complex -> real (DHT done) ------
// g_bufB [v][x][y][k3] -> out real [v][k1][y][k3]; out = (to_out? outp : g_X), scaled.
__global__ void __launch_bounds__(288) k_fft_x_fold(float* __restrict__ outp, int to_out, float scale)
{
    __shared__ float2 tile[48][48];   // [x][k3]
    __shared__ float2 tw[48];         // (cas+, cas-) = (c+s, c-s)
    int v = blockIdx.x / 48, y = blockIdx.x % 48;
    int tid = threadIdx.x;
    if (tid < 48) { float s, c; sincospif(tid * (2.0f / 48.0f), &s, &c); tw[tid] = make_float2(c + s, c - s); }
    const float2* base = g_bufB + (size_t)v * N3 + (size_t)y * 48;
    for (int idx = tid; idx < N2; idx += 288) {
        int xx = idx / 48, z = idx % 48;
        tile[xx][z] = base[(size_t)xx * N2 + z];
    }
    __syncthreads();

    float* ob = (to_out ? outp : (float*)g_X) + (size_t)v * N3 + (size_t)y * 48;
    int z = tid % 48, kb = tid / 48;
    #pragma unroll
    for (int it = 0; it < 8; ++it) {
        int k1 = kb * 8 + it;
        float a = 0.f;
        int j = 0;
        #pragma unroll
        for (int xx = 0; xx < 48; ++xx) {
            float2 vv = tile[xx][z];
            float2 t = tw[j];
            a = fmaf(t.x, vv.x, fmaf(-t.y, vv.y, a));   // cas(th)*re - cas(-th)*im
            j = wrap48(j + k1);
        }
        ob[(size_t)k1 * N2 + z] = a * scale;
    }
}

// ---------------- Y (kernel spectrum) stage: sparse 12^3 support ----------------
// c1[io][m1][m2][k3]  (in g_bufB), c2[io][m1][k2][k3] (in g_bufA), then g_Y real.
__global__ void __launch_bounds__(192) k_y1(const float* __restrict__ w)
{
    __shared__ float  wt[1728];
    __shared__ float2 tw[48];
    int io = blockIdx.x;
    int tid = threadIdx.x;
    if (tid < 48) { float s, c; sincospif(tid * (2.0f / 48.0f), &s, &c); tw[tid] = make_float2(c, s); }
    for (int idx = tid; idx < 1728; idx += 192) wt[idx] = w[(size_t)io * 1728 + idx];
    __syncthreads();

    float2* c1 = g_bufB;
    int k = tid % 48, mb = tid / 48;   // mb 0..3
    float2* ob = c1 + (size_t)io * (144 * 48);
    for (int it = 0; it < 36; ++it) {
        int mm = mb * 36 + it;         // m1*12+m2 in [0,144)
        float ar = 0.f, ai = 0.f;
        int j = 0;
        #pragma unroll
        for (int m3 = 0; m3 < 12; ++m3) {
            float vv = wt[mm * 12 + m3];
            float2 t = tw[j];
            ar = fmaf(t.x, vv, ar);
            ai = fmaf(-t.y, vv, ai);
            j = wrap48(j + k);
        }
        ob[mm * 48 + k] = make_float2(ar, ai);
    }
}

__global__ void __launch_bounds__(288) k_y2()
{
    __shared__ float2 tile[12][48];
    __shared__ float2 tw[48];
    int io = blockIdx.x / 12, m1 = blockIdx.x % 12;
    int tid = threadIdx.x;
    if (tid < 48) { float s, c; sincospif(tid * (2.0f / 48.0f), &s, &c); tw[tid] = make_float2(c, s); }
    const float2* c1 = g_bufB;
    const float2* base = c1 + (size_t)io * 6912 + (size_t)m1 * 576;
    for (int idx = tid; idx < 576; idx += 288) tile[idx / 48][idx % 48] = base[idx];
    __syncthreads();

    float2* c2 = g_bufA;
    int k3 = tid % 48, kb = tid / 48;
    float2* ob = c2 + (size_t)io * (12 * 2304) + (size_t)m1 * 2304;
    #pragma unroll
    for (int it = 0; it < 8; ++it) {
        int k2 = kb * 8 + it;
        float ar = 0.f, ai = 0.f;
        int j = 0;
        #pragma unroll
        for (int m2 = 0; m2 < 12; ++m2) {
            float2 vv = tile[m2][k3];
            float2 t = tw[j];
            ar = fmaf(t.x, vv.x, fmaf( t.y, vv.y, ar));
            ai = fmaf(t.x, vv.y, fmaf(-t.y, vv.x, ai));
            j = wrap48(j + k2);
        }
        ob[k2 * 48 + k3] = make_float2(ar, ai);
    }
}

__global__ void __launch_bounds__(288) k_y3()
{
    __shared__ float2 tile[12][48];
    __shared__ float2 tw[48];         // (cas+, cas-)
    int io = blockIdx.x / 48, k2 = blockIdx.x % 48;
    int tid = threadIdx.x;
    if (tid < 48) { float s, c; sincospif(tid * (2.0f / 48.0f), &s, &c); tw[tid] = make_float2(c + s, c - s); }
    const float2* c2 = g_bufA;
    const float2* base = c2 + (size_t)io * 27648 + (size_t)k2 * 48;
    for (int idx = tid; idx < 576; idx += 288) {
        int m1 = idx / 48, k3 = idx % 48;
        tile[m1][k3] = base[(size_t)m1 * 2304 + k3];
    }
    __syncthreads();

    int k3 = tid % 48, kb = tid / 48;
    float* ob = g_Y + (size_t)io * N3 + (size_t)k2 * 48;
    #pragma unroll
    for (int it = 0; it < 8; ++it) {
        int k1 = kb * 8 + it;
        float a = 0.f;
        int j = 0;
        #pragma unroll
        for (int m1 = 0; m1 < 12; ++m1) {
            float2 vv = tile[m1][k3];
            float2 t = tw[j];
            a = fmaf(t.x, vv.x, fmaf(-t.y, vv.y, a));
            j = wrap48(j + k1);
        }
        ob[(size_t)k1 * N2 + k3] = a;
    }
}

// ---------------- Mixing: Z[p] = 0.5*[(Xp+Xq)*Yp + (Xp-Xq)*Yq], q = (p? n-p : 0) ----------------
__global__ void __launch_bounds__(256) k_mix()
{
    __shared__ float Sx[16][132];   // [pp][i*8+b], row stride 132 (bank-safe, 16B aligned)
    __shared__ float Dx[16][132];
    int p0 = blockIdx.x * 16;
    int tid = threadIdx.x;

    for (int idx = tid; idx < 2048; idx += 256) {
        int bi = idx >> 4;          // b*16+i
        int pp = idx & 15;
        int p = p0 + pp;
        int q = (p == 0) ? 0 : (N3 - p);
        float xp = g_X[(size_t)bi * N3 + p];
        float xq = g_X[(size_t)bi * N3 + q];
        int b = bi >> 4, i = bi & 15;
        Sx[pp][i * 8 + b] = xp + xq;
        Dx[pp][i * 8 + b] = xp - xq;
    }
    __syncthreads();

    int o = tid >> 4, pp = tid & 15;
    int p = p0 + pp;
    int q = (p == 0) ? 0 : (N3 - p);
    float acc[8];
    #pragma unroll
    for (int b = 0; b < 8; ++b) acc[b] = 0.f;

    #pragma unroll
    for (int i = 0; i < 16; ++i) {
        float yp = g_Y[(size_t)(i * 16 + o) * N3 + p];
        float yq = g_Y[(size_t)(i * 16 + o) * N3 + q];
        const float4* sp = (const float4*)&Sx[pp][i * 8];
        const float4* dp = (const float4*)&Dx[pp][i * 8];
        float4 s0 = sp[0], s1 = sp[1];
        float4 d0 = dp[0], d1 = dp[1];
        acc[0] = fmaf(s0.x, yp, fmaf(d0.x, yq, acc[0]));
        acc[1] = fmaf(s0.y, yp, fmaf(d0.y, yq, acc[1]));
        acc[2] = fmaf(s0.z, yp, fmaf(d0.z, yq, acc[2]));
        acc[3] = fmaf(s0.w, yp, fmaf(d0.w, yq, acc[3]));
        acc[4] = fmaf(s1.x, yp, fmaf(d1.x, yq, acc[4]));
        acc[5] = fmaf(s1.y, yp, fmaf(d1.y, yq, acc[5]));
        acc[6] = fmaf(s1.z, yp, fmaf(d1.z, yq, acc[6]));
        acc[7] = fmaf(s1.w, yp, fmaf(d1.w, yq, acc[7]));
    }
    #pragma unroll
    for (int b = 0; b < 8; ++b)
        g_Z[(size_t)(b * 16 + o) * N3 + p] = 0.5f * acc[b];
}

extern "C" void kernel_launch(void* const* d_in, const int* in_sizes, int n_in,
                              void* d_out, int out_size)
{
    (void)in_sizes; (void)n_in; (void)out_size;
    const float* x = (const float*)d_in[0];
    // d_in[1] = error_signal (all zeros -> full modes; unused by reference math)
    const float* w = (const float*)d_in[2];
    float* outp = (float*)d_out;

    // Y = DHT3(zero-padded weights)   [uses g_bufB (c1) and g_bufA (c2) as temps]
    k_y1<<<NIO, 192>>>(w);
    k_y2<<<NIO * 12, 288>>>();
    k_y3<<<NIO * 48, 288>>>();

    // X = DHT3(x)
    k_fft_z<<<NVOL * 48, 288>>>(x, 0);
    k_fft_y<<<NVOL * 48, 288>>>();
    k_fft_x_fold<<<NVOL * 48, 288>>>(nullptr, 0, 1.0f);

    // Z = mix(X, Y)
    k_mix<<<N3 / 16, 256>>>();

    // out = DHT3(Z) / n
    k_fft_z<<<NVOL * 48, 288>>>(nullptr, 1);
    k_fft_y<<<NVOL * 48, 288>>>();
    k_fft_x_fold<<<NVOL * 48, 288>>>(outp, 1, 1.0f / (float)N3);
}